// round 16
// baseline (speedup 1.0000x reference)
#include <cuda_runtime.h>
#include <cstdint>

#define NMAX 50000
#define EMAX 800000

// ---------------- scratch (device globals) -----------------------------------
__device__ __align__(256) float g_h1[NMAX * 128];    // layer1 features [N,2,64]
__device__ __align__(256) float g_h2[NMAX * 64];     // layer2 features [N,2,32]
__device__ __align__(256) float g_asrc1[NMAX * 2], g_adst1[NMAX * 2];
__device__ __align__(256) float g_asrc2[NMAX * 2], g_adst2[NMAX * 2];
__device__ __align__(256) int   g_cnt[NMAX];         // in-degree counts / cursors
__device__ __align__(256) int   g_ptr[NMAX + 1];     // CSR row pointers
__device__ __align__(256) int   g_csr[EMAX];         // CSR source ids

// ---------------- helpers ----------------------------------------------------
__device__ __forceinline__ float lrelu(float x) { return x > 0.f ? x : 0.2f * x; }

// ---------------- CSR build --------------------------------------------------
__global__ void zero_kernel(int n) {
    int i = blockIdx.x * blockDim.x + threadIdx.x;
    if (i < n) g_cnt[i] = 0;
}

__global__ void count_kernel(const int* __restrict__ ei, int E) {
    int i = blockIdx.x * blockDim.x + threadIdx.x;
    if (i < E) atomicAdd(&g_cnt[ei[E + i]], 1);
}

// single-block exclusive scan of g_cnt[0..n) -> g_ptr (shfl-based)
__global__ void scan_kernel(int n) {
    __shared__ int warp_off[32];
    __shared__ int carry_sm;
    const int tid = threadIdx.x, lane = tid & 31, wid = tid >> 5;
    if (tid == 0) { g_ptr[0] = 0; carry_sm = 0; }
    __syncthreads();
    for (int base = 0; base < n; base += 1024) {
        int i = base + tid;
        int v = (i < n) ? g_cnt[i] : 0;
        int x = v;
#pragma unroll
        for (int o = 1; o < 32; o <<= 1) {
            int t = __shfl_up_sync(0xffffffffu, x, o);
            if (lane >= o) x += t;
        }
        if (lane == 31) warp_off[wid] = x;
        __syncthreads();
        if (wid == 0) {
            int w = warp_off[lane];
            int y = w;
#pragma unroll
            for (int o = 1; o < 32; o <<= 1) {
                int t = __shfl_up_sync(0xffffffffu, y, o);
                if (lane >= o) y += t;
            }
            warp_off[lane] = y - w;  // exclusive offsets
        }
        __syncthreads();
        int incl = x + warp_off[wid] + carry_sm;
        if (i < n) g_ptr[i + 1] = incl;
        __syncthreads();
        if (tid == 1023) carry_sm = incl;
        __syncthreads();
    }
}

// scatter with atomicSub on counts (cursor-free; leaves g_cnt at 0)
__global__ void scatter_kernel(const int* __restrict__ ei, int E) {
    int i = blockIdx.x * blockDim.x + threadIdx.x;
    if (i >= E) return;
    int s = ei[i], d = ei[E + i];
    int pos = atomicSub(&g_cnt[d], 1) - 1;
    g_csr[g_ptr[d] + pos] = s;
}

// ---------------- GEMM1 + fused attention projections (layer 1) --------------
// g_h1[n,j] = sum_k x[n,k]*W1[k,j]; epilogue computes asrc1/adst1 per node+head.
__global__ void gemm1_kernel(const float* __restrict__ A, const float* __restrict__ W,
                             const float* __restrict__ att_src, const float* __restrict__ att_dst,
                             int n_rows) {
    constexpr int COLT = 32;   // threads across columns (float4 each)
    constexpr int RPT  = 8;    // rows per thread

    __shared__ float x_sm[64][36];
    __shared__ float w_sm[32][128];

    const int row0 = blockIdx.x * 64;
    const int tid  = threadIdx.x;
    const int tj   = tid % COLT;
    const int tn   = tid / COLT;
    const int lane = tid & 31;

    float acc[RPT][4];
#pragma unroll
    for (int i = 0; i < RPT; i++) { acc[i][0] = acc[i][1] = acc[i][2] = acc[i][3] = 0.f; }

    for (int kt = 0; kt < 128; kt += 32) {
        __syncthreads();
#pragma unroll
        for (int l = 0; l < 2; l++) {
            int i = tid + l * 256;
            int r = i >> 3, c4 = i & 7;
            float4 v = make_float4(0.f, 0.f, 0.f, 0.f);
            if (row0 + r < n_rows)
                v = *(const float4*)&A[(size_t)(row0 + r) * 128 + kt + c4 * 4];
            x_sm[r][c4 * 4 + 0] = v.x;
            x_sm[r][c4 * 4 + 1] = v.y;
            x_sm[r][c4 * 4 + 2] = v.z;
            x_sm[r][c4 * 4 + 3] = v.w;
        }
#pragma unroll
        for (int i = tid; i < 32 * 32; i += 256) {
            int r = i >> 5, c4 = i & 31;
            *(float4*)&w_sm[r][c4 * 4] = *(const float4*)&W[(size_t)(kt + r) * 128 + c4 * 4];
        }
        __syncthreads();
#pragma unroll
        for (int k = 0; k < 32; k++) {
            float4 w = *(float4*)&w_sm[k][tj * 4];
#pragma unroll
            for (int i = 0; i < RPT; i++) {
                float xv = x_sm[tn * RPT + i][k];
                acc[i][0] += xv * w.x;
                acc[i][1] += xv * w.y;
                acc[i][2] += xv * w.z;
                acc[i][3] += xv * w.w;
            }
        }
    }

    const float4 avs = *(const float4*)&att_src[tj * 4];
    const float4 avd = *(const float4*)&att_dst[tj * 4];

#pragma unroll
    for (int i = 0; i < RPT; i++) {
        int r = row0 + tn * RPT + i;
        if (r < n_rows) {
            *(float4*)&g_h1[(size_t)r * 128 + tj * 4] =
                make_float4(acc[i][0], acc[i][1], acc[i][2], acc[i][3]);
            float ps = acc[i][0] * avs.x + acc[i][1] * avs.y + acc[i][2] * avs.z + acc[i][3] * avs.w;
            float pd = acc[i][0] * avd.x + acc[i][1] * avd.y + acc[i][2] * avd.z + acc[i][3] * avd.w;
#pragma unroll
            for (int o = 1; o < 16; o <<= 1) {
                ps += __shfl_xor_sync(0xffffffffu, ps, o);
                pd += __shfl_xor_sync(0xffffffffu, pd, o);
            }
            float ps1 = __shfl_sync(0xffffffffu, ps, lane + 16);
            float pd1 = __shfl_sync(0xffffffffu, pd, lane + 16);
            if (tj == 0) {
                ((float2*)g_asrc1)[r] = make_float2(ps, ps1);
                ((float2*)g_adst1)[r] = make_float2(pd, pd1);
            }
        }
    }
}

// ---------------- fused layer1 aggregate + GEMM2 + attn2 ---------------------
// 512 threads = 16 warps. Phase A: warp w aggregates dst row d0+w (softmax-
// weighted neighbor sum, bias+relu) -> smem. Phase B: warps 0-3 compute the
// 16x64 h2 tile against smem-resident W2 and the layer2 attention projections.
__global__ __launch_bounds__(512) void gat_layer1_fused(
        const float* __restrict__ bias1, const float* __restrict__ W2,
        const float* __restrict__ att_src2, const float* __restrict__ att_dst2, int n) {
    __shared__ float W2s[128][64];   // 32 KB
    __shared__ float rs[16][128];    // 8 KB staged relu rows

    const int tid  = threadIdx.x;
    const int w    = tid >> 5;
    const int lane = tid & 31;
    const int d0   = blockIdx.x * 16;

    // cooperative W2 load (consumed after the barrier below)
#pragma unroll
    for (int j = 0; j < 4; j++)
        ((float4*)W2s)[tid + j * 512] = ((const float4*)W2)[tid + j * 512];

    // ---- phase A ----
    const int d = d0 + w;
    if (d < n) {
        const int p0 = g_ptr[d], p1 = g_ptr[d + 1];
        const float2 ad    = ((const float2*)g_adst1)[d];
        const float2 aself = ((const float2*)g_asrc1)[d];
        const bool  h0lane = (lane < 16);
        const float adH = h0lane ? ad.x : ad.y;

        float wgt = __expf(lrelu((h0lane ? aself.x : aself.y) + adH));
        float4 hv = *(const float4*)&g_h1[(size_t)d * 128 + lane * 4];
        float4 acc = make_float4(wgt * hv.x, wgt * hv.y, wgt * hv.z, wgt * hv.w);
        float ssum = wgt;
#pragma unroll 2
        for (int i = p0; i < p1; i++) {
            int s = g_csr[i];
            const float2 as = ((const float2*)g_asrc1)[s];
            float wt = __expf(lrelu((h0lane ? as.x : as.y) + adH));
            hv = *(const float4*)&g_h1[(size_t)s * 128 + lane * 4];
            acc.x += wt * hv.x; acc.y += wt * hv.y;
            acc.z += wt * hv.z; acc.w += wt * hv.w;
            ssum += wt;
        }
        float inv = 1.f / (ssum + 1e-16f);
        float4 b = *(const float4*)&bias1[lane * 4];
        acc.x = fmaxf(acc.x * inv + b.x, 0.f);
        acc.y = fmaxf(acc.y * inv + b.y, 0.f);
        acc.z = fmaxf(acc.z * inv + b.z, 0.f);
        acc.w = fmaxf(acc.w * inv + b.w, 0.f);
        *(float4*)&rs[w][lane * 4] = acc;
    }
    __syncthreads();

    // ---- phase B: 4 warps, warp w handles rows 4w..4w+3, lane = 2 cols -----
    if (w < 4) {
        float2 acc2[4];
#pragma unroll
        for (int rr = 0; rr < 4; rr++) acc2[rr] = make_float2(0.f, 0.f);

#pragma unroll 4
        for (int k = 0; k < 128; k++) {
            float2 w2 = *(float2*)&W2s[k][lane * 2];
#pragma unroll
            for (int rr = 0; rr < 4; rr++) {
                float rv = rs[4 * w + rr][k];
                acc2[rr].x += rv * w2.x;
                acc2[rr].y += rv * w2.y;
            }
        }

        const float2 avs = *(const float2*)&att_src2[lane * 2];
        const float2 avd = *(const float2*)&att_dst2[lane * 2];
#pragma unroll
        for (int rr = 0; rr < 4; rr++) {
            int r = d0 + 4 * w + rr;
            if (r < n) {
                *(float2*)&g_h2[(size_t)r * 64 + lane * 2] = acc2[rr];
                float ps = acc2[rr].x * avs.x + acc2[rr].y * avs.y;
                float pd = acc2[rr].x * avd.x + acc2[rr].y * avd.y;
#pragma unroll
                for (int o = 1; o < 16; o <<= 1) {
                    ps += __shfl_xor_sync(0xffffffffu, ps, o);
                    pd += __shfl_xor_sync(0xffffffffu, pd, o);
                }
                float ps1 = __shfl_sync(0xffffffffu, ps, lane + 16);
                float pd1 = __shfl_sync(0xffffffffu, pd, lane + 16);
                if (lane == 0) {
                    ((float2*)g_asrc2)[r] = make_float2(ps, ps1);
                    ((float2*)g_adst2)[r] = make_float2(pd, pd1);
                }
            }
        }
    }
}

// ---------------- fused layer2: single-sweep aggregate + mean + bias ---------
__global__ void gat_layer2_fused(const float* __restrict__ bias,
                                 float* __restrict__ out, int n) {
    const int d    = (blockIdx.x * blockDim.x + threadIdx.x) >> 5;
    const int lane = threadIdx.x & 31;
    if (d >= n) return;

    const int p0 = g_ptr[d], p1 = g_ptr[d + 1];
    const float2 ad    = ((const float2*)g_adst2)[d];
    const float2 aself = ((const float2*)g_asrc2)[d];
    const bool  h0lane = (lane < 16);
    const float adH = h0lane ? ad.x : ad.y;

    float wgt = __expf(lrelu((h0lane ? aself.x : aself.y) + adH));
    float2 hv = *(const float2*)&g_h2[(size_t)d * 64 + lane * 2];
    float2 acc = make_float2(wgt * hv.x, wgt * hv.y);
    float ssum = wgt;
#pragma unroll 2
    for (int i = p0; i < p1; i++) {
        int s = g_csr[i];
        const float2 as = ((const float2*)g_asrc2)[s];
        float wt = __expf(lrelu((h0lane ? as.x : as.y) + adH));
        hv = *(const float2*)&g_h2[(size_t)s * 64 + lane * 2];
        acc.x += wt * hv.x; acc.y += wt * hv.y;
        ssum += wt;
    }
    float inv = 1.f / (ssum + 1e-16f);
    acc.x *= inv; acc.y *= inv;
    float ox = __shfl_xor_sync(0xffffffffu, acc.x, 16);
    float oy = __shfl_xor_sync(0xffffffffu, acc.y, 16);
    if (lane < 16) {
        float2 o;
        o.x = 0.5f * (acc.x + ox) + bias[lane * 2];
        o.y = 0.5f * (acc.y + oy) + bias[lane * 2 + 1];
        *(float2*)&out[(size_t)d * 32 + lane * 2] = o;
    }
}

// ---------------- launch -----------------------------------------------------
extern "C" void kernel_launch(void* const* d_in, const int* in_sizes, int n_in,
                              void* d_out, int out_size) {
    const float* x   = (const float*)d_in[0];
    const int*   ei  = (const int*)d_in[1];
    const float* W1  = (const float*)d_in[2];
    const float* as1 = (const float*)d_in[3];
    const float* ad1 = (const float*)d_in[4];
    const float* b1  = (const float*)d_in[5];
    const float* W2  = (const float*)d_in[6];
    const float* as2 = (const float*)d_in[7];
    const float* ad2 = (const float*)d_in[8];
    const float* b2  = (const float*)d_in[9];
    float*       out = (float*)d_out;

    const int N = in_sizes[0] / 128;
    const int E = in_sizes[1] / 2;

    // Fork a side stream for the CSR build so it overlaps gemm1.
    cudaStream_t s2;
    cudaStreamCreateWithFlags(&s2, cudaStreamNonBlocking);
    cudaEvent_t ev_fork, ev_join;
    cudaEventCreateWithFlags(&ev_fork, cudaEventDisableTiming);
    cudaEventCreateWithFlags(&ev_join, cudaEventDisableTiming);

    cudaEventRecord(ev_fork, 0);
    cudaStreamWaitEvent(s2, ev_fork, 0);

    zero_kernel<<<(N + 255) / 256, 256, 0, s2>>>(N);
    count_kernel<<<(E + 255) / 256, 256, 0, s2>>>(ei, E);
    scan_kernel<<<1, 1024, 0, s2>>>(N);
    scatter_kernel<<<(E + 255) / 256, 256, 0, s2>>>(ei, E);
    cudaEventRecord(ev_join, s2);

    gemm1_kernel<<<(N + 63) / 64, 256>>>(x, W1, as1, ad1, N);

    cudaStreamWaitEvent(0, ev_join, 0);

    gat_layer1_fused<<<(N + 15) / 16, 512>>>(b1, W2, as2, ad2, N);
    gat_layer2_fused<<<(N * 32 + 255) / 256, 256>>>(b2, out, N);

    cudaEventDestroy(ev_fork);
    cudaEventDestroy(ev_join);
    cudaStreamDestroy(s2);
}